// round 13
// baseline (speedup 1.0000x reference)
#include <cuda_runtime.h>
#include <cstdint>

#define BATCH  16
#define MAXLEN 128
#define NTOK   (BATCH * MAXLEN)   // 2048
#define VOCAB  32128
#define V4     (VOCAB / 4)        // 8032
#define EMB    768

// ---------------------------------------------------------------------------
// Bit-exact replication of:
//   coord = jnp.linspace(-1, 1, size)[h]
//     JAX linspace (num>1): s = iota(f32 h)/f32(div); out = start*(1-s)+stop*s,
//     endpoint appended exactly as `stop`.
//   ix = ((coord + 1.0)*size - 1.0)/2.0 ;  round half-even ; clip [0, size-1]
// All ops forced to un-fused f32 (XLA emits separate rounded mul/add HLOs).
// ---------------------------------------------------------------------------
__device__ __forceinline__ int nearest_idx_rep(int h, int size) {
    float coord;
    if (h == size - 1) {
        coord = 1.0f;                                     // endpoint set to stop
    } else {
        float s = __fdiv_rn((float)h, (float)(size - 1)); // iota/div
        float t = __fsub_rn(1.0f, s);                     // (1 - step)
        float a = __fmul_rn(-1.0f, t);                    // start*(1-step)
        coord   = __fadd_rn(a, s);                        // + stop*step
    }
    float u1 = __fadd_rn(coord, 1.0f);
    float u2 = __fmul_rn(u1, (float)size);
    float u3 = __fsub_rn(u2, 1.0f);
    float ix = __fdiv_rn(u3, 2.0f);
    float r  = rintf(ix);                                 // round half-to-even
    r = fminf(fmaxf(r, 0.0f), (float)(size - 1));
    return (int)r;
}

// ---------------------------------------------------------------------------
// Single mega-kernel, STREAM-FIRST ordering: one block per token, 2048 blocks.
// __launch_bounds__(256, 7): occ 7 -> 1036 concurrent blocks -> 2048 tokens
// split 1036 + 1012: two nearly perfectly balanced waves (the R5 config that
// sustained 6525 GB/s), and lower oe on the cross-CTA L1tex-contention slope.
//
// Phase 1 (at entry, no prologue bubble): first-occurrence argmax over V of
//   (logits + gumbel). Pure HBM stream, 526 MB over the grid.
// Phase 2 (post-loop, hidden under other blocks' streams): per-batch passage
//   bookkeeping (mask/psg rows L2-hot: 128 blocks/batch):
//     psg_r    = roll(psg_ids, 1) with BOS=1
//     extr[k]  = (1 - mask[L-1-k]) * psg_r[k]
//     trunc[k] = extr[(k - sum(mask)) mod L]
//     flag[k]  = any_{i<=k} trunc[i] != 0  -> rb = flag[j] ? trunc[j] : -1
// Phase 3: ra = mask[j] ? nearest_idx(argmax) : -1, then dual gather:
//   out[tok,e] = (ra>=0 ? WE[ra,col(e)] : 0) + (rb>=0 ? WE[rb,col(e)] : 0)
// col(e) replicates _nearest_idx over linspace(-1,1,EMB) exactly (identity).
// ---------------------------------------------------------------------------
__global__ __launch_bounds__(256, 7) void k_all(
    const float4* __restrict__ lg, const float4* __restrict__ gm,
    const int* __restrict__ mask, const int* __restrict__ psg,
    const float* __restrict__ we, float* __restrict__ out)
{
    const int tok = blockIdx.x;
    const int tid = threadIdx.x;

    __shared__ int   s_mask[MAXLEN];
    __shared__ int   s_extr[MAXLEN];
    __shared__ int   s_red[4];
    __shared__ int   s_rb;
    __shared__ float sv[8];
    __shared__ int   si[8];

    // ---- phase 1: streaming argmax (starts immediately) ----
    const float4* L = lg + (size_t)tok * V4;
    const float4* G = gm + (size_t)tok * V4;

    float best = -3.402823466e38f;
    int   bi   = 0;

    #pragma unroll 4
    for (int i = tid; i < V4; i += 256) {
        float4 a = __ldg(&L[i]);
        float4 c = __ldg(&G[i]);
        float v0 = __fadd_rn(a.x, c.x);
        float v1 = __fadd_rn(a.y, c.y);
        float v2 = __fadd_rn(a.z, c.z);
        float v3 = __fadd_rn(a.w, c.w);
        int base = i << 2;
        // per-thread indices strictly increase -> '>' keeps first occurrence
        if (v0 > best) { best = v0; bi = base;     }
        if (v1 > best) { best = v1; bi = base + 1; }
        if (v2 > best) { best = v2; bi = base + 2; }
        if (v3 > best) { best = v3; bi = base + 3; }
    }

    // ---- phase 2: issue tiny L2-hot loads, hide under the shuffle reduce ----
    const int b = tok >> 7;             // batch
    const int j = tok & (MAXLEN - 1);   // position within batch
    int m = 0, pj = 0;
    if (tid < MAXLEN) {
        m  = __ldg(&mask[b * MAXLEN + tid]);
        pj = (tid == 0) ? 1 : __ldg(&psg[b * MAXLEN + tid - 1]);
    }

    // (maxval, min-index-on-tie) semilattice reduce == jnp.argmax semantics
    #pragma unroll
    for (int o = 16; o > 0; o >>= 1) {
        float ov = __shfl_down_sync(0xffffffffu, best, o);
        int   oi = __shfl_down_sync(0xffffffffu, bi,   o);
        if (ov > best || (ov == best && oi < bi)) { best = ov; bi = oi; }
    }
    if ((tid & 31) == 0) { sv[tid >> 5] = best; si[tid >> 5] = bi; }
    if (tid < MAXLEN) s_mask[tid] = m;
    __syncthreads();

    if (tid < MAXLEN) {
        s_extr[tid] = (1 - s_mask[MAXLEN - 1 - tid]) * pj;
        unsigned wsum = __reduce_add_sync(0xffffffffu, (unsigned)m);
        if ((tid & 31) == 0) s_red[tid >> 5] = (int)wsum;
    }
    __syncthreads();

    if (tid < MAXLEN) {
        int shifts = s_red[0] + s_red[1] + s_red[2] + s_red[3];
        int pos    = (tid - shifts + MAXLEN) & (MAXLEN - 1);
        int tr     = s_extr[pos];
        if (tid == j) s_rb = tr;                 // provisional: trunc[j]
        int key = (tr != 0) ? tid : MAXLEN;
        unsigned wmin = __reduce_min_sync(0xffffffffu, (unsigned)key);
        if ((tid & 31) == 0) s_red[tid >> 5] = (int)wmin;
    }
    __syncthreads();

    if (tid == 0) {
        int firstnz = min(min(s_red[0], s_red[1]), min(s_red[2], s_red[3]));
        if (j < firstnz) s_rb = -1;              // leading zeros -> no embed
        // final argmax reduce across the 8 warps
        best = sv[0]; bi = si[0];
        #pragma unroll
        for (int w = 1; w < 8; w++) {
            if (sv[w] > best || (sv[w] == best && si[w] < bi)) {
                best = sv[w]; bi = si[w];
            }
        }
        // ra: grid_sample-nearest row for the argmax token (or -1 if masked)
        si[0] = s_mask[j] ? nearest_idx_rep(bi, VOCAB) : -1;
    }
    __syncthreads();

    // ---- phase 3: dual gather + store (coalesced: WE rows contiguous) ----
    const int ra = si[0];
    const int rb = s_rb;

    #pragma unroll
    for (int e = tid; e < EMB; e += 256) {
        int col = nearest_idx_rep(e, EMB);
        float v = 0.0f;
        if (ra >= 0) v = __ldg(&we[(size_t)ra * EMB + col]);
        if (rb >= 0) v = __fadd_rn(v, __ldg(&we[(size_t)rb * EMB + col]));
        out[(size_t)tok * EMB + e] = v;
    }
}

// ---------------------------------------------------------------------------
// Entry point. Inputs (metadata order):
//   0: logits           f32 [16,128,32128]
//   1: rwrt_attn_mask   i32 [16,128]
//   2: psg_input_ids    i32 [16,128]
//   3: word_embeddings  f32 [32128,768]
//   4: gumbel_noise     f32 [16,128,32128]
// Output: f32 [16,128,768]
// ---------------------------------------------------------------------------
extern "C" void kernel_launch(void* const* d_in, const int* in_sizes, int n_in,
                              void* d_out, int out_size)
{
    const float* logits = (const float*)d_in[0];
    const int*   mask   = (const int*)  d_in[1];
    const int*   psg    = (const int*)  d_in[2];
    const float* we     = (const float*)d_in[3];
    const float* gum    = (const float*)d_in[4];
    float*       out    = (float*)d_out;

    k_all<<<NTOK, 256>>>((const float4*)logits, (const float4*)gum,
                         mask, psg, we, out);
}

// round 14
// speedup vs baseline: 1.2354x; 1.2354x over previous
#include <cuda_runtime.h>
#include <cstdint>

#define BATCH  16
#define MAXLEN 128
#define NTOK   (BATCH * MAXLEN)   // 2048
#define VOCAB  32128
#define V4     (VOCAB / 4)        // 8032
#define EMB    768
#define EMB4   (EMB / 4)          // 192

// ---------------------------------------------------------------------------
// Bit-exact replication of:
//   coord = jnp.linspace(-1, 1, size)[h]
//     JAX linspace (num>1): s = iota(f32 h)/f32(div); out = start*(1-s)+stop*s,
//     endpoint appended exactly as `stop`.
//   ix = ((coord + 1.0)*size - 1.0)/2.0 ;  round half-even ; clip [0, size-1]
// All ops forced to un-fused f32 (XLA emits separate rounded mul/add HLOs).
// (Used once per block for the vocab row; the EMB column map is provably the
//  identity — rint(e - 0.5 + e/767) == e, e=0 half-even clips to 0 — which the
//  rel_err=0 runs of the scalar path confirmed.)
// ---------------------------------------------------------------------------
__device__ __forceinline__ int nearest_idx_rep(int h, int size) {
    float coord;
    if (h == size - 1) {
        coord = 1.0f;                                     // endpoint set to stop
    } else {
        float s = __fdiv_rn((float)h, (float)(size - 1)); // iota/div
        float t = __fsub_rn(1.0f, s);                     // (1 - step)
        float a = __fmul_rn(-1.0f, t);                    // start*(1-step)
        coord   = __fadd_rn(a, s);                        // + stop*step
    }
    float u1 = __fadd_rn(coord, 1.0f);
    float u2 = __fmul_rn(u1, (float)size);
    float u3 = __fsub_rn(u2, 1.0f);
    float ix = __fdiv_rn(u3, 2.0f);
    float r  = rintf(ix);                                 // round half-to-even
    r = fminf(fmaxf(r, 0.0f), (float)(size - 1));
    return (int)r;
}

// ---------------------------------------------------------------------------
// Single mega-kernel (R11 base config: occ 8, __ldcs, stream-first), one
// block per token, PLUS the algorithmic cut: masked tokens (mask[tok]==0)
// skip the argmax stream entirely — their inputs_embeds row is multiplied by
// zero in the reference and `hot` feeds nothing else. ~25% of the 526 MB
// stream is dead work (lens ~ U[64,128]).
//
// Phase 1 (live tokens only): first-occurrence argmax over V of
//   (logits + gumbel). Pure HBM stream, evict-first so WE rows stay in L2.
// Phase 2: per-batch passage bookkeeping (mask/psg rows L2-hot):
//   psg_r    = roll(psg_ids, 1) with BOS=1
//   extr[k]  = (1 - mask[L-1-k]) * psg_r[k]
//   trunc[k] = extr[(k - sum(mask)) mod L]
//   flag[k]  = any_{i<=k} trunc[i] != 0  -> rb = flag[j] ? trunc[j] : -1
// Phase 3: ra = mask[j] ? nearest_idx(argmax) : -1, float4 dual gather:
//   out[tok,e] = (ra>=0 ? WE[ra,e] : 0) + (rb>=0 ? WE[rb,e] : 0)
// ---------------------------------------------------------------------------
__global__ __launch_bounds__(256, 8) void k_all(
    const float4* __restrict__ lg, const float4* __restrict__ gm,
    const int* __restrict__ mask, const int* __restrict__ psg,
    const float4* __restrict__ we4, float4* __restrict__ out4)
{
    const int tok = blockIdx.x;
    const int tid = threadIdx.x;

    __shared__ int   s_mask[MAXLEN];
    __shared__ int   s_extr[MAXLEN];
    __shared__ int   s_red[4];
    __shared__ int   s_rb;
    __shared__ float sv[8];
    __shared__ int   si[8];

    // block-uniform liveness check (single broadcast address, L2-hot)
    const int mj = __ldg(&mask[tok]);

    float best = -3.402823466e38f;
    int   bi   = 0;

    if (mj) {
        // ---- phase 1: streaming argmax (live tokens only) ----
        const float4* L = lg + (size_t)tok * V4;
        const float4* G = gm + (size_t)tok * V4;

        #pragma unroll 4
        for (int i = tid; i < V4; i += 256) {
            float4 a = __ldcs(&L[i]);
            float4 c = __ldcs(&G[i]);
            float v0 = __fadd_rn(a.x, c.x);
            float v1 = __fadd_rn(a.y, c.y);
            float v2 = __fadd_rn(a.z, c.z);
            float v3 = __fadd_rn(a.w, c.w);
            int base = i << 2;
            // per-thread indices strictly increase -> '>' keeps first occurrence
            if (v0 > best) { best = v0; bi = base;     }
            if (v1 > best) { best = v1; bi = base + 1; }
            if (v2 > best) { best = v2; bi = base + 2; }
            if (v3 > best) { best = v3; bi = base + 3; }
        }
    }

    // ---- phase 2: issue tiny L2-hot loads, hide under the shuffle reduce ----
    const int b = tok >> 7;             // batch
    const int j = tok & (MAXLEN - 1);   // position within batch
    int m = 0, pj = 0;
    if (tid < MAXLEN) {
        m  = __ldg(&mask[b * MAXLEN + tid]);
        pj = (tid == 0) ? 1 : __ldg(&psg[b * MAXLEN + tid - 1]);
    }

    // (maxval, min-index-on-tie) semilattice reduce == jnp.argmax semantics
    #pragma unroll
    for (int o = 16; o > 0; o >>= 1) {
        float ov = __shfl_down_sync(0xffffffffu, best, o);
        int   oi = __shfl_down_sync(0xffffffffu, bi,   o);
        if (ov > best || (ov == best && oi < bi)) { best = ov; bi = oi; }
    }
    if ((tid & 31) == 0) { sv[tid >> 5] = best; si[tid >> 5] = bi; }
    if (tid < MAXLEN) s_mask[tid] = m;
    __syncthreads();

    if (tid < MAXLEN) {
        s_extr[tid] = (1 - s_mask[MAXLEN - 1 - tid]) * pj;
        unsigned wsum = __reduce_add_sync(0xffffffffu, (unsigned)m);
        if ((tid & 31) == 0) s_red[tid >> 5] = (int)wsum;
    }
    __syncthreads();

    if (tid < MAXLEN) {
        int shifts = s_red[0] + s_red[1] + s_red[2] + s_red[3];
        int pos    = (tid - shifts + MAXLEN) & (MAXLEN - 1);
        int tr     = s_extr[pos];
        if (tid == j) s_rb = tr;                 // provisional: trunc[j]
        int key = (tr != 0) ? tid : MAXLEN;
        unsigned wmin = __reduce_min_sync(0xffffffffu, (unsigned)key);
        if ((tid & 31) == 0) s_red[tid >> 5] = (int)wmin;
    }
    __syncthreads();

    if (tid == 0) {
        int firstnz = min(min(s_red[0], s_red[1]), min(s_red[2], s_red[3]));
        if (j < firstnz) s_rb = -1;              // leading zeros -> no embed
        // final argmax reduce across the 8 warps
        best = sv[0]; bi = si[0];
        #pragma unroll
        for (int w = 1; w < 8; w++) {
            if (sv[w] > best || (sv[w] == best && si[w] < bi)) {
                best = sv[w]; bi = si[w];
            }
        }
        // ra: grid_sample-nearest row for the argmax token (or -1 if masked)
        si[0] = mj ? nearest_idx_rep(bi, VOCAB) : -1;
    }
    __syncthreads();

    // ---- phase 3: float4 dual gather + store (WE rows 16B-aligned) ----
    const int ra = si[0];
    const int rb = s_rb;

    if (tid < EMB4) {
        float4 v = make_float4(0.f, 0.f, 0.f, 0.f);
        if (ra >= 0) v = __ldg(&we4[(size_t)ra * EMB4 + tid]);
        if (rb >= 0) {
            float4 w = __ldg(&we4[(size_t)rb * EMB4 + tid]);
            v.x = __fadd_rn(v.x, w.x);
            v.y = __fadd_rn(v.y, w.y);
            v.z = __fadd_rn(v.z, w.z);
            v.w = __fadd_rn(v.w, w.w);
        }
        out4[(size_t)tok * EMB4 + tid] = v;
    }
}

// ---------------------------------------------------------------------------
// Entry point. Inputs (metadata order):
//   0: logits           f32 [16,128,32128]
//   1: rwrt_attn_mask   i32 [16,128]
//   2: psg_input_ids    i32 [16,128]
//   3: word_embeddings  f32 [32128,768]
//   4: gumbel_noise     f32 [16,128,32128]
// Output: f32 [16,128,768]
// ---------------------------------------------------------------------------
extern "C" void kernel_launch(void* const* d_in, const int* in_sizes, int n_in,
                              void* d_out, int out_size)
{
    const float* logits = (const float*)d_in[0];
    const int*   mask   = (const int*)  d_in[1];
    const int*   psg    = (const int*)  d_in[2];
    const float* we     = (const float*)d_in[3];
    const float* gum    = (const float*)d_in[4];

    k_all<<<NTOK, 256>>>((const float4*)logits, (const float4*)gum,
                         mask, psg, (const float4*)we, (float4*)d_out);
}